// round 17
// baseline (speedup 1.0000x reference)
#include <cuda_runtime.h>

#define N_MAX     1048576
#define SEGS      (64 * 4096)   // 262144 segments
#define NB        64            // batches
#define GRID_DIM  64
#define NUM_CELLS 4096
#define SPLIT     4             // blocks per batch
#define CELLS_PB  1024          // cells gathered per block (NUM_CELLS/SPLIT)
#define STAGE_MAX 5120          // staged pids per gather block (20KB)

// ---- scratch (static device globals) ----
__device__ int g_pids[N_MAX];            // point ids grouped by cell
__device__ int g_offsets[SEGS + 1];      // exclusive prefix + sentinel
__device__ int g_hcnt[SPLIT][SEGS];      // per-split per-cell counts
__device__ int g_syncA[NB];              // hist published   (reset in-kernel)
__device__ int g_syncB[NB];              // pids ready       (reset in-kernel)
__device__ int g_syncC[NB];              // gather done      (reset in-kernel)

// warp-collective 32-ary lower_bound over sorted int array:
// returns smallest i with a[i] >= tgt (n if none). ~4 probe rounds for n=1M.
__device__ __forceinline__ int lower_bound32(const int* __restrict__ a, int n,
                                             int tgt) {
    int lane = threadIdx.x & 31;
    int lo = -1, hi = n;                 // invariant: a[lo] < tgt <= a[hi]
    while (hi - lo > 1) {
        int span = hi - lo;
        int step = (span + 32) / 33;
        int p = lo + (lane + 1) * step;
        bool ge = (p >= hi) ? true : (a[p] >= tgt);
        unsigned m = __ballot_sync(0xffffffffu, ge);
        if (m == 0) {
            lo += 32 * step;
        } else {
            int k = __ffs(m) - 1;
            int nh = lo + (k + 1) * step; if (nh > hi) nh = hi;
            lo = lo + k * step;
            hi = nh;
        }
    }
    return hi;
}

// per-batch single-hop sync among the SPLIT sibling blocks
__device__ __forceinline__ void batch_sync(int* ctr) {
    __syncthreads();
    if (threadIdx.x == 0) {
        __threadfence();
        atomicAdd(ctr, 1);
        while (atomicAdd(ctr, 0) < SPLIT) { __nanosleep(40); }
        __threadfence();
    }
    __syncthreads();
}

// ---------------------------------------------------------------
// FUSED prep+gather. 256 blocks x 1024 thr, all co-resident (2 blocks/SM).
// Block (b,k): prep quarter k of batch b, per-batch sync, then gather cells
// [k*1024,(k+1)*1024) of batch b. Batches pipeline independently: early
// batches' DRAM-bound gather overlaps late batches' latency-bound prep.
// batch is SORTED int32 (JAX x64 disabled => int64 requests materialize int32).
__global__ void __launch_bounds__(1024, 2)
k_fused(const float4* __restrict__ x4, const int2* __restrict__ pos,
        const int* __restrict__ batch, float4* __restrict__ out4, int n) {
    __shared__ __align__(16) int s_cnt[NUM_CELLS];   // counts -> cursors
    __shared__ int ws[32], wexcl[32];
    __shared__ int s_lo, s_hi;
    __shared__ int s_off[CELLS_PB + 1];
    __shared__ int s_pid[STAGE_MAX];

    int bk   = blockIdx.x;
    int b    = bk >> 2;
    int k    = bk & 3;
    int tid  = threadIdx.x;
    int lane = tid & 31;
    int wid  = tid >> 5;

    // ---------------- PREP ----------------
    ((int4*)s_cnt)[tid] = make_int4(0, 0, 0, 0);
    if (wid == 0) {
        int r = lower_bound32(batch, n, b);
        if (lane == 0) s_lo = r;
    } else if (wid == 1) {
        int r = lower_bound32(batch, n, b + 1);
        if (lane == 0) s_hi = r;
    }
    __syncthreads();

    int lo   = s_lo;
    int hi   = s_hi;
    int len  = hi - lo;
    int qlen = (len + SPLIT - 1) / SPLIT;
    int plo  = lo + k * qlen;
    int phi  = plo + qlen < hi ? plo + qlen : hi;
    if (phi < plo) phi = plo;

    // pass 1: smem histogram of my quarter
    for (int i = plo + tid; i < phi; i += 1024) {
        int2 p = pos[i];
        atomicAdd(&s_cnt[(p.x >> 2) * GRID_DIM + (p.y >> 2)], 1);
    }
    __syncthreads();

    // publish my counts; sync siblings
    int4 mine = ((int4*)s_cnt)[tid];
    ((int4*)&g_hcnt[k][b * NUM_CELLS])[tid] = mine;
    batch_sync(&g_syncA[b]);

    // combine splits: tot = sum_j cnt_j, pre = sum_{j<k} cnt_j
    int4 tot = mine;
    int4 pre = make_int4(0, 0, 0, 0);
    #pragma unroll
    for (int j = 0; j < SPLIT; j++) {
        if (j == k) continue;
        int4 o = ((const int4*)&g_hcnt[j][b * NUM_CELLS])[tid];
        tot.x += o.x; tot.y += o.y; tot.z += o.z; tot.w += o.w;
        if (j < k) { pre.x += o.x; pre.y += o.y; pre.z += o.z; pre.w += o.w; }
    }

    // block scan of per-thread totals (4 cells/thread)
    int sum  = tot.x + tot.y + tot.z + tot.w;
    int incl = sum;
    #pragma unroll
    for (int d = 1; d < 32; d <<= 1) {
        int u = __shfl_up_sync(0xffffffffu, incl, d);
        if (lane >= d) incl += u;
    }
    if (lane == 31) ws[wid] = incl;
    __syncthreads();
    if (wid == 0) {
        int w = ws[lane];
        int wi = w;
        #pragma unroll
        for (int d = 1; d < 32; d <<= 1) {
            int u = __shfl_up_sync(0xffffffffu, wi, d);
            if (lane >= d) wi += u;
        }
        wexcl[lane] = wi - w;
    }
    __syncthreads();
    int e0 = incl - sum + wexcl[wid];
    int e1 = e0 + tot.x;
    int e2 = e1 + tot.y;
    int e3 = e2 + tot.z;

    // absolute cursors for my split; offsets written once (split 0)
    ((int4*)s_cnt)[tid] = make_int4(lo + e0 + pre.x, lo + e1 + pre.y,
                                    lo + e2 + pre.z, lo + e3 + pre.w);
    if (k == 0) {
        ((int4*)&g_offsets[b * NUM_CELLS])[tid] =
            make_int4(lo + e0, lo + e1, lo + e2, lo + e3);
        if (b == NB - 1 && tid == 1023)
            g_offsets[SEGS] = n;           // sentinel
    }
    __syncthreads();

    // pass 2: place pids (pos re-read is L2-hot; regs stay under the cap)
    for (int i = plo + tid; i < phi; i += 1024) {
        int2 p = pos[i];
        int c = (p.x >> 2) * GRID_DIM + (p.y >> 2);
        int r = atomicAdd(&s_cnt[c], 1);
        g_pids[r] = i;
    }
    batch_sync(&g_syncB[b]);               // all 4 splits' pids visible

    // ---------------- GATHER (cells [k*1024,(k+1)*1024) of batch b) --------
    int cbase = b * NUM_CELLS + k * CELLS_PB;

    if (tid < 257) {                        // 1025 offsets, 4 per thread + 1
        #pragma unroll
        for (int q = 0; q < 4; q++) {
            int c = tid * 4 + q;
            if (c <= CELLS_PB) s_off[c] = g_offsets[cbase + c];
        }
    }
    __syncthreads();

    int base0 = s_off[0];
    int total = s_off[CELLS_PB] - base0;
    bool all_staged = (total <= STAGE_MAX);
    int stage = all_staged ? total : 0;
    for (int i = tid; i < stage; i += 1024)
        s_pid[i] = g_pids[base0 + i];
    __syncthreads();

    int g = lane >> 4;           // half-warp id (0/1)
    int s = lane & 15;           // float4 column within 64-ch row
    const float ninf = __int_as_float(0xff800000);

    for (int it = 0; it < CELLS_PB / 128; it++) {   // 8 groups of 4 cells/warp
        int cA = it * 128 + wid * 4 + g * 2;
        int cB = cA + 1;

        int offA = s_off[cA],  offB = s_off[cB];
        int cntA = s_off[cA + 1] - offA;
        int cntB = s_off[cB + 1] - offB;
        int lsA  = offA - base0,  lsB = offB - base0;

        float4 accA = make_float4(ninf, ninf, ninf, ninf);
        float4 accB = make_float4(ninf, ninf, ninf, ninf);

        if (all_staged) {
            int lo2 = cntA < cntB ? cntA : cntB;
            #pragma unroll 2
            for (int j = 0; j < lo2; j++) {        // branch-free bulk
                int pA = s_pid[lsA + j];
                int pB = s_pid[lsB + j];
                float4 vA = x4[pA * 16 + s];
                float4 vB = x4[pB * 16 + s];
                accA.x = fmaxf(accA.x, vA.x);
                accA.y = fmaxf(accA.y, vA.y);
                accA.z = fmaxf(accA.z, vA.z);
                accA.w = fmaxf(accA.w, vA.w);
                accB.x = fmaxf(accB.x, vB.x);
                accB.y = fmaxf(accB.y, vB.y);
                accB.z = fmaxf(accB.z, vB.z);
                accB.w = fmaxf(accB.w, vB.w);
            }
            for (int j = lo2; j < cntA; j++) {     // A remainder
                float4 v = x4[s_pid[lsA + j] * 16 + s];
                accA.x = fmaxf(accA.x, v.x);
                accA.y = fmaxf(accA.y, v.y);
                accA.z = fmaxf(accA.z, v.z);
                accA.w = fmaxf(accA.w, v.w);
            }
            for (int j = lo2; j < cntB; j++) {     // B remainder
                float4 v = x4[s_pid[lsB + j] * 16 + s];
                accB.x = fmaxf(accB.x, v.x);
                accB.y = fmaxf(accB.y, v.y);
                accB.z = fmaxf(accB.z, v.z);
                accB.w = fmaxf(accB.w, v.w);
            }
        } else {                                    // rare fallback
            int jm = cntA > cntB ? cntA : cntB;
            for (int j = 0; j < jm; j++) {
                if (j < cntA) {
                    float4 v = x4[g_pids[offA + j] * 16 + s];
                    accA.x = fmaxf(accA.x, v.x);
                    accA.y = fmaxf(accA.y, v.y);
                    accA.z = fmaxf(accA.z, v.z);
                    accA.w = fmaxf(accA.w, v.w);
                }
                if (j < cntB) {
                    float4 v = x4[g_pids[offB + j] * 16 + s];
                    accB.x = fmaxf(accB.x, v.x);
                    accB.y = fmaxf(accB.y, v.y);
                    accB.z = fmaxf(accB.z, v.z);
                    accB.w = fmaxf(accB.w, v.w);
                }
            }
        }

        if (cntA == 0) accA = make_float4(0.f, 0.f, 0.f, 0.f);
        if (cntB == 0) accB = make_float4(0.f, 0.f, 0.f, 0.f);
        out4[(cbase + cA) * 16 + s] = accA;        // 16 lanes -> 256B row
        out4[(cbase + cB) * 16 + s] = accB;
    }

    // ---- sync-state reset for next graph replay (batch-local) ----
    __syncthreads();
    if (tid == 0) {
        __threadfence();
        atomicAdd(&g_syncC[b], 1);
        if (k == 0) {
            while (atomicAdd(&g_syncC[b], 0) < SPLIT) { __nanosleep(40); }
            g_syncA[b] = 0;
            g_syncB[b] = 0;
            g_syncC[b] = 0;
            __threadfence();
        }
    }
}

// ---------------------------------------------------------------
extern "C" void kernel_launch(void* const* d_in, const int* in_sizes, int n_in,
                              void* d_out, int out_size) {
    const float* x     = (const float*)d_in[0];
    const int2*  pos   = (const int2*)d_in[1];
    const int*   batch = (const int*)d_in[2];
    float* out = (float*)d_out;
    int n = in_sizes[2];     // number of points

    k_fused<<<NB * SPLIT, 1024>>>((const float4*)x, pos, batch,
                                  (float4*)out, n);
}